// round 15
// baseline (speedup 1.0000x reference)
#include <cuda_runtime.h>
#include <cuda_fp16.h>
#include <cstdint>

#define BATCH 8
#define SEQ   4096
#define DM    65
#define DH    64
#define NUNITS 640u
#define ONE2  0x3C003C00u   // half2(1.0, 1.0)

// Scratch (__device__ globals; allocation-free rule)
__device__ __half g_q [BATCH * SEQ * DH];         // pre-scaled log2(e)/sqrt(65)
__device__ __half g_k [BATCH * SEQ * DH];
__device__ __half g_vT[BATCH * DH * SEQ];         // [b][dim][l]
__device__ float  g_part [8 * 32 * 4 * 128 * 64]; // partial O per (tile, chunk)
__device__ float  g_lpart[8 * 32 * 4 * 128];      // partial row-sums
__device__ unsigned int g_tile_ctr;               // persistent work queue

// ============================ helpers ============================
__device__ __forceinline__ uint32_t smem_u32(const void* p) {
    uint32_t a;
    asm("{ .reg .u64 t; cvta.to.shared.u64 t, %1; cvt.u32.u64 %0, t; }" : "=r"(a) : "l"(p));
    return a;
}
__device__ __forceinline__ void ldsm4(uint32_t addr, uint32_t r[4]) {
    asm volatile("ldmatrix.sync.aligned.m8n8.x4.shared.b16 {%0,%1,%2,%3}, [%4];"
                 : "=r"(r[0]), "=r"(r[1]), "=r"(r[2]), "=r"(r[3]) : "r"(addr));
}
__device__ __forceinline__ void ldsm4t(uint32_t addr, uint32_t r[4]) {
    asm volatile("ldmatrix.sync.aligned.m8n8.x4.trans.shared.b16 {%0,%1,%2,%3}, [%4];"
                 : "=r"(r[0]), "=r"(r[1]), "=r"(r[2]), "=r"(r[3]) : "r"(addr));
}
// D(16x8,f32) += A(16x16,f16) * B(16x8,f16)
__device__ __forceinline__ void mma_f16(float c[4], const uint32_t a[4],
                                        uint32_t b0, uint32_t b1) {
    asm volatile(
        "mma.sync.aligned.m16n8k16.row.col.f32.f16.f16.f32 "
        "{%0,%1,%2,%3}, {%4,%5,%6,%7}, {%8,%9}, {%0,%1,%2,%3};"
        : "+f"(c[0]), "+f"(c[1]), "+f"(c[2]), "+f"(c[3])
        : "r"(a[0]), "r"(a[1]), "r"(a[2]), "r"(a[3]), "r"(b0), "r"(b1));
}
__device__ __forceinline__ uint32_t pkh2(float a, float b) {
    __half2 h = __floats2half2_rn(a, b);
    return *reinterpret_cast<uint32_t*>(&h);
}
__device__ __forceinline__ uint32_t ex2h2(uint32_t x) {  // 2^x on packed half2
    uint32_t r; asm("ex2.approx.f16x2 %0, %1;" : "=r"(r) : "r"(x));
    return r;
}
__device__ __forceinline__ void cpa16(uint32_t s, const void* g) {
    asm volatile("cp.async.cg.shared.global [%0], [%1], 16;" :: "r"(s), "l"(g) : "memory");
}
#define CP_COMMIT() asm volatile("cp.async.commit_group;" ::: "memory")
#define CP_WAIT0()  asm volatile("cp.async.wait_group 0;" ::: "memory")
#define CP_WAIT1()  asm volatile("cp.async.wait_group 1;" ::: "memory")
#define CP_WAIT2()  asm volatile("cp.async.wait_group 2;" ::: "memory")
// fp16 tile row = 64 halfs = 128B = 8 chunks of 16B; chunk XOR-swizzled by row&7
__device__ __forceinline__ uint32_t swzh(int row, int ch) {
    return (uint32_t)((row << 7) + (((ch ^ (row & 7))) << 4));
}

// ============================ tensor-core projections ============================
// Block = 384 threads = 3 warpgroups (wg 0: Q scaled, 1: K, 2: V^T) over 128 rows
// of x. x staged ONCE, shared by all three GEMMs; each wg stages its own W and
// runs independently after one sync. K=65: 64 dims via MMA + fp32 rank-1 + bias.
__global__ void __launch_bounds__(384) proj_kernel(
    const float* __restrict__ x,
    const float* __restrict__ Wq, const float* __restrict__ bq,
    const float* __restrict__ Wk, const float* __restrict__ bk,
    const float* __restrict__ Wv, const float* __restrict__ bv)
{
    __shared__ __align__(16) __half sX[128 * 64];
    __shared__ __align__(16) __half sWh[3][64 * 64];
    __shared__ float sx64[128];
    __shared__ float sw64[3][64];
    __shared__ float sbias[3][64];

    const int tid    = threadIdx.x;
    const int wg     = tid / 128;          // phase
    const int wg_tid = tid % 128;
    const int lane   = tid & 31;
    const int w      = (wg_tid >> 5);      // warp within wg (0..3)
    const int row0   = blockIdx.x << 7;
    const uint32_t sXb = smem_u32(sX);
    const uint32_t sWb = smem_u32(sWh[wg]);
    char* sXc = (char*)sX;
    char* sWc = (char*)sWh[wg];

    if (blockIdx.x == 0 && tid == 0) g_tile_ctr = 0u;

    const float* W    = (wg == 0) ? Wq : (wg == 1) ? Wk : Wv;
    const float* bias = (wg == 0) ? bq : (wg == 1) ? bk : bv;

    // ---- stage x tile once (all 384 threads) ----
    for (int f = tid; f < 4096; f += 384) {
        const int row = f >> 5, d2 = f & 31;
        const size_t gb = (size_t)(row0 + row) * DM + 2 * d2;
        *(uint32_t*)(sXc + swzh(row, d2 >> 2) + ((d2 & 3) << 2)) = pkh2(x[gb], x[gb + 1]);
    }
    if (tid < 128) sx64[tid] = x[(size_t)(row0 + tid) * DM + 64];

    // ---- each wg stages its own W (fp16 swizzled) + remainder row + bias ----
    #pragma unroll
    for (int i = 0; i < 8; i++) {
        const int f = wg_tid + i * 128;
        const int d = f >> 4, c4 = (f & 15) << 2;
        const float4 v = *(const float4*)&W[d * 64 + c4];
        char* p = sWc + swzh(d, c4 >> 3) + ((c4 & 7) << 1);
        *(uint32_t*)p       = pkh2(v.x, v.y);
        *(uint32_t*)(p + 4) = pkh2(v.z, v.w);
    }
    if (wg_tid < 64) { sw64[wg][wg_tid] = W[64 * 64 + wg_tid]; sbias[wg][wg_tid] = bias[wg_tid]; }
    __syncthreads();

    const int rA = lane & 15, cA = lane >> 4;
    const int rB = (lane & 7) + ((lane >> 4) << 3), cB = (lane >> 3) & 1;
    const int i0 = lane >> 2, q2 = (lane & 3) << 1;

    if (wg < 2) {
        const float sc = (wg == 0) ? 0.17894429839f : 1.0f;  // log2(e)/sqrt(65)
        __half* dst = (wg == 0) ? g_q : g_k;

        uint32_t qa[2][4][4];
        #pragma unroll
        for (int rb = 0; rb < 2; rb++)
            #pragma unroll
            for (int ks = 0; ks < 4; ks++)
                ldsm4(sXb + swzh(32 * w + 16 * rb + rA, 2 * ks + cA), qa[rb][ks]);

        float acc[2][8][4];
        #pragma unroll
        for (int rb = 0; rb < 2; rb++)
            #pragma unroll
            for (int t = 0; t < 8; t++)
                #pragma unroll
                for (int e = 0; e < 4; e++) acc[rb][t][e] = 0.f;

        #pragma unroll
        for (int ks = 0; ks < 4; ks++)
            #pragma unroll
            for (int tp = 0; tp < 4; tp++) {
                uint32_t bt[4];
                ldsm4t(sWb + swzh(16 * ks + rA, 2 * tp + cA), bt);
                #pragma unroll
                for (int rb = 0; rb < 2; rb++) {
                    mma_f16(acc[rb][2 * tp],     qa[rb][ks], bt[0], bt[1]);
                    mma_f16(acc[rb][2 * tp + 1], qa[rb][ks], bt[2], bt[3]);
                }
            }

        #pragma unroll
        for (int rb = 0; rb < 2; rb++) {
            const int r0l = 32 * w + 16 * rb + i0;
            const int r1l = r0l + 8;
            const float x0 = sx64[r0l], x1 = sx64[r1l];
            #pragma unroll
            for (int t = 0; t < 8; t++) {
                const int col = 8 * t + q2;
                const float b0 = sbias[wg][col], b1 = sbias[wg][col + 1];
                const float w0 = sw64[wg][col], w1 = sw64[wg][col + 1];
                *(uint32_t*)&dst[(size_t)(row0 + r0l) * 64 + col] =
                    pkh2((acc[rb][t][0] + b0 + x0 * w0) * sc, (acc[rb][t][1] + b1 + x0 * w1) * sc);
                *(uint32_t*)&dst[(size_t)(row0 + r1l) * 64 + col] =
                    pkh2((acc[rb][t][2] + b0 + x1 * w0) * sc, (acc[rb][t][3] + b1 + x1 * w1) * sc);
            }
        }
    } else {
        // V^T: D[dim][l] = Wv^T x^T (trans-A on W tile, x tile as B)
        uint32_t aw[4][4];
        #pragma unroll
        for (int ks = 0; ks < 4; ks++)
            ldsm4t(sWb + swzh(16 * ks + rB, 2 * w + cB), aw[ks]);

        float acc[16][4];
        #pragma unroll
        for (int t = 0; t < 16; t++)
            #pragma unroll
            for (int e = 0; e < 4; e++) acc[t][e] = 0.f;

        #pragma unroll
        for (int tpl = 0; tpl < 8; tpl++)
            #pragma unroll
            for (int ks = 0; ks < 4; ks++) {
                uint32_t xb[4];
                ldsm4(sXb + swzh(16 * tpl + rB, 2 * ks + cB), xb);
                mma_f16(acc[2 * tpl],     aw[ks], xb[0], xb[1]);
                mma_f16(acc[2 * tpl + 1], aw[ks], xb[2], xb[3]);
            }

        const int bb = row0 >> 12, l0 = row0 & 4095;
        const int dim0 = 16 * w + i0, dim1 = dim0 + 8;
        const float bw0 = sbias[2][dim0], bw1 = sbias[2][dim1];
        const float w0 = sw64[2][dim0], w1 = sw64[2][dim1];
        #pragma unroll
        for (int t = 0; t < 16; t++) {
            const int col = 8 * t + q2;
            const float xa = sx64[col], xb2 = sx64[col + 1];
            *(uint32_t*)&g_vT[(size_t)((bb << 6) + dim0) * SEQ + l0 + col] =
                pkh2(acc[t][0] + bw0 + w0 * xa, acc[t][1] + bw0 + w0 * xb2);
            *(uint32_t*)&g_vT[(size_t)((bb << 6) + dim1) * SEQ + l0 + col] =
                pkh2(acc[t][2] + bw1 + w1 * xa, acc[t][3] + bw1 + w1 * xb2);
        }
    }
}

// ============================ flash (fp16 mma, split-K, P in registers) ============================
// Softmax: pack masked fp32 scores to half2, one ex2.approx.f16x2 -> P fragment
// directly. Row-sums via ones-MMA (l = P x 1).
__global__ void __launch_bounds__(128, 2) flash_kernel()
{
    __shared__ __align__(16) __half sK[2][64 * 64];
    __shared__ __align__(16) __half sV[2][64 * 64];
    __shared__ __align__(16) __half sQ[128 * 64];   // Q staging; [0] aliased as queue slot

    const uint32_t sKb[2] = { smem_u32(sK[0]), smem_u32(sK[1]) };
    const uint32_t sVb[2] = { smem_u32(sV[0]), smem_u32(sV[1]) };
    const uint32_t sQb = smem_u32(sQ);

    const int tid  = threadIdx.x;
    const int lane = tid & 31;
    const int w    = tid >> 5;
    const int rowA = lane & 15;
    const int chA  = lane >> 4;
    const int rowB = (lane & 7) + ((lane >> 4) << 3);
    const int chB  = (lane >> 3) & 1;
    const int i0   = lane >> 2;
    const int q2   = (lane & 3) << 1;

    for (;;) {
        if (tid == 0)
            *(volatile unsigned*)sQ = atomicAdd(&g_tile_ctr, 1u);
        __syncthreads();
        const unsigned unit = *(volatile unsigned*)sQ;
        __syncthreads();
        if (unit >= NUNITS) break;

        // decode: heavy-first (qt descending), chunks of 16 K-iterations
        const int r = (int)(unit >> 3);
        const int b = (int)(unit & 7u);
        int qt, ch;
        if (r < 32)      { qt = 31 - (r >> 2); ch = r & 3; }
        else if (r < 56) { const int t = r - 32; const int q3 = t / 3; qt = 23 - q3; ch = t - 3 * q3; }
        else if (r < 72) { const int t = r - 56; qt = 15 - (t >> 1); ch = t & 1; }
        else             { qt = 7 - (r - 72); ch = 0; }
        const int nkt = 2 * qt + 2;
        const int kt0 = ch << 4;
        const int kt1 = (kt0 + 16 < nkt) ? kt0 + 16 : nkt;
        const int q0  = qt << 7;

        // ---- async fills: Q, then K/V stage 0 and 1 ----
        #pragma unroll
        for (int i = 0; i < 8; i++) {
            const int f = tid + i * 128;
            const int row = f >> 3, cc = f & 7;
            cpa16(sQb + swzh(row, cc), &g_q[(size_t)((b << 12) + q0 + row) * 64 + cc * 8]);
        }
        CP_COMMIT();
        {
            const int k0 = kt0 << 6;
            #pragma unroll
            for (int i = 0; i < 4; i++) {
                const int f = tid + i * 128;
                const int row = f >> 3, cc = f & 7;
                cpa16(sKb[0] + swzh(row, cc), &g_k[(size_t)((b << 12) + k0 + row) * 64 + cc * 8]);
                cpa16(sVb[0] + swzh(row, cc), &g_vT[(size_t)((b << 6) + row) * SEQ + k0 + cc * 8]);
            }
            CP_COMMIT();
        }
        const bool has2 = (kt0 + 1 < kt1);
        if (has2) {
            const int k0 = (kt0 + 1) << 6;
            #pragma unroll
            for (int i = 0; i < 4; i++) {
                const int f = tid + i * 128;
                const int row = f >> 3, cc = f & 7;
                cpa16(sKb[1] + swzh(row, cc), &g_k[(size_t)((b << 12) + k0 + row) * 64 + cc * 8]);
                cpa16(sVb[1] + swzh(row, cc), &g_vT[(size_t)((b << 6) + row) * SEQ + k0 + cc * 8]);
            }
            CP_COMMIT();
            CP_WAIT2();   // Q group retired
        } else {
            CP_WAIT1();
        }
        __syncthreads();

        // ---- Q fragments (A): 2 row-blocks x 4 k-steps ----
        uint32_t qa[2][4][4];
        #pragma unroll
        for (int rb = 0; rb < 2; rb++)
            #pragma unroll
            for (int ks = 0; ks < 4; ks++)
                ldsm4(sQb + swzh(32 * w + 16 * rb + rowA, 2 * ks + chA), qa[rb][ks]);

        float o[2][8][4];
        #pragma unroll
        for (int rb = 0; rb < 2; rb++)
            #pragma unroll
            for (int t = 0; t < 8; t++)
                #pragma unroll
                for (int e = 0; e < 4; e++) o[rb][t][e] = 0.f;
        float rsacc[2][4];
        #pragma unroll
        for (int rb = 0; rb < 2; rb++)
            #pragma unroll
            for (int e = 0; e < 4; e++) rsacc[rb][e] = 0.f;

        for (int kt = kt0; kt < kt1; kt++) {
            const int cur = (kt - kt0) & 1;
            const int k0  = kt << 6;

            if (kt + 1 < kt1) { CP_WAIT1(); } else { CP_WAIT0(); }
            __syncthreads();   // buf[cur] filled & visible

            // ---- MMA1: S = Q K^T (all 32 mma back-to-back) ----
            float s[2][8][4];
            #pragma unroll
            for (int t = 0; t < 8; t++)
                #pragma unroll
                for (int e = 0; e < 4; e++) { s[0][t][e] = 0.f; s[1][t][e] = 0.f; }
            #pragma unroll
            for (int ks = 0; ks < 4; ks++)
                #pragma unroll
                for (int tp = 0; tp < 4; tp++) {
                    uint32_t kb[4];
                    ldsm4(sKb[cur] + swzh(16 * tp + rowB, 2 * ks + chB), kb);
                    mma_f16(s[0][2 * tp],     qa[0][ks], kb[0], kb[1]);
                    mma_f16(s[0][2 * tp + 1], qa[0][ks], kb[2], kb[3]);
                    mma_f16(s[1][2 * tp],     qa[1][ks], kb[0], kb[1]);
                    mma_f16(s[1][2 * tp + 1], qa[1][ks], kb[2], kb[3]);
                }

            // ---- softmax: mask (fp32), pack half2, ex2.f16x2 -> P A-frags ----
            const bool diag = (kt >= 2 * qt);
            uint32_t pa[2][4][4];
            #pragma unroll
            for (int rb = 0; rb < 2; rb++) {
                const int r0 = q0 + 32 * w + 16 * rb + i0;
                const int r1 = r0 + 8;
                #pragma unroll
                for (int t = 0; t < 8; t++) {
                    float s0 = s[rb][t][0], s1 = s[rb][t][1];
                    float s2 = s[rb][t][2], s3 = s[rb][t][3];
                    if (diag) {
                        const int key = k0 + 8 * t + q2;
                        if (key     > r0) s0 = -1e30f;   // -> half -inf -> ex2 = 0
                        if (key + 1 > r0) s1 = -1e30f;
                        if (key     > r1) s2 = -1e30f;
                        if (key + 1 > r1) s3 = -1e30f;
                    }
                    const uint32_t p01 = ex2h2(pkh2(s0, s1));
                    const uint32_t p23 = ex2h2(pkh2(s2, s3));
                    const int ks = t >> 1;
                    if ((t & 1) == 0) {
                        pa[rb][ks][0] = p01;
                        pa[rb][ks][1] = p23;
                    } else {
                        pa[rb][ks][2] = p01;
                        pa[rb][ks][3] = p23;
                    }
                }
            }

            // ---- MMA2: O += P V ; row-sums via ones-MMA (l = P x 1) ----
            #pragma unroll
            for (int ks = 0; ks < 4; ks++) {
                #pragma unroll
                for (int tp = 0; tp < 4; tp++) {
                    uint32_t vb[4];
                    ldsm4(sVb[cur] + swzh(16 * tp + rowB, 2 * ks + chB), vb);
                    mma_f16(o[0][2 * tp],     pa[0][ks], vb[0], vb[1]);
                    mma_f16(o[0][2 * tp + 1], pa[0][ks], vb[2], vb[3]);
                    mma_f16(o[1][2 * tp],     pa[1][ks], vb[0], vb[1]);
                    mma_f16(o[1][2 * tp + 1], pa[1][ks], vb[2], vb[3]);
                }
                mma_f16(rsacc[0], pa[0][ks], ONE2, ONE2);
                mma_f16(rsacc[1], pa[1][ks], ONE2, ONE2);
            }

            __syncthreads();   // all reads of buf[cur] complete
            if (kt + 2 < kt1) {
                const int kn = (kt + 2) << 6;
                #pragma unroll
                for (int i = 0; i < 4; i++) {
                    const int f = tid + i * 128;
                    const int row = f >> 3, cc = f & 7;
                    cpa16(sKb[cur] + swzh(row, cc), &g_k[(size_t)((b << 12) + kn + row) * 64 + cc * 8]);
                    cpa16(sVb[cur] + swzh(row, cc), &g_vT[(size_t)((b << 6) + row) * SEQ + kn + cc * 8]);
                }
                CP_COMMIT();
            }
        }

        // ---- epilogue: write un-normalized partials; l from ones-MMA accum ----
        const int slot = (((b << 5) + qt) << 2) + ch;
        float* po = &g_part[(size_t)slot << 13];
        #pragma unroll
        for (int rb = 0; rb < 2; rb++) {
            const int r0l = 32 * w + 16 * rb + i0;
            float* o0 = &po[r0l * 64];
            float* o1 = o0 + 8 * 64;
            #pragma unroll
            for (int t = 0; t < 8; t++) {
                *(float2*)&o0[8 * t + q2] = make_float2(o[rb][t][0], o[rb][t][1]);
                *(float2*)&o1[8 * t + q2] = make_float2(o[rb][t][2], o[rb][t][3]);
            }
            if ((lane & 3) == 0) {
                g_lpart[slot * 128 + r0l]     = rsacc[rb][0];   // row i0 sum
                g_lpart[slot * 128 + r0l + 8] = rsacc[rb][2];   // row i0+8 sum
            }
        }
    }
}

// ============================ normalize / combine ============================
__global__ void __launch_bounds__(256) norm_kernel(float* __restrict__ out)
{
    const int tile = blockIdx.x;
    const int b = tile >> 5, qt = tile & 31;
    const int nc = (qt + 8) >> 3;
    const int tid = threadIdx.x;
    const int row = tid >> 1;
    const int c0  = (tid & 1) << 5;
    const size_t base = (size_t)tile << 15;

    float acc[32];
    #pragma unroll
    for (int i = 0; i < 32; i++) acc[i] = 0.f;
    float l = 0.f;

    for (int c = 0; c < nc; c++) {
        const float* p = &g_part[base + ((size_t)c << 13) + row * 64 + c0];
        #pragma unroll
        for (int i = 0; i < 8; i++) {
            const float4 v = *(const float4*)&p[i * 4];
            acc[4 * i]     += v.x;
            acc[4 * i + 1] += v.y;
            acc[4 * i + 2] += v.z;
            acc[4 * i + 3] += v.w;
        }
        l += g_lpart[(tile * 4 + c) * 128 + row];
    }
    const float inv = 1.f / l;
    float* po = &out[(size_t)((b << 12) + (qt << 7) + row) * 64 + c0];
    #pragma unroll
    for (int i = 0; i < 8; i++)
        *(float4*)&po[i * 4] = make_float4(acc[4*i] * inv, acc[4*i+1] * inv,
                                           acc[4*i+2] * inv, acc[4*i+3] * inv);
}

// ============================ launch ============================
extern "C" void kernel_launch(void* const* d_in, const int* in_sizes, int n_in,
                              void* d_out, int out_size)
{
    const float* x  = (const float*)d_in[0];
    const float* Wq = (const float*)d_in[1];
    const float* bq = (const float*)d_in[2];
    const float* Wk = (const float*)d_in[3];
    const float* bk = (const float*)d_in[4];
    const float* Wv = (const float*)d_in[5];
    const float* bv = (const float*)d_in[6];
    float* out = (float*)d_out;

    proj_kernel<<<(BATCH * SEQ) / 128, 384>>>(x, Wq, bq, Wk, bk, Wv, bv);
    flash_kernel<<<296, 128>>>();          // persistent, 2 CTAs/SM, 640 units
    norm_kernel<<<256, 256>>>(out);
}

// round 16
// speedup vs baseline: 1.1359x; 1.1359x over previous
#include <cuda_runtime.h>
#include <cuda_fp16.h>
#include <cstdint>

#define BATCH 8
#define SEQ   4096
#define DM    65
#define DH    64
#define NUNITS 640u
#define ONE2  0x3C003C00u   // half2(1.0, 1.0)

// Scratch (__device__ globals; allocation-free rule)
__device__ __half g_q [BATCH * SEQ * DH];         // pre-scaled log2(e)/sqrt(65)
__device__ __half g_k [BATCH * SEQ * DH];
__device__ __half g_vT[BATCH * DH * SEQ];         // [b][dim][l]
__device__ __half g_part [8 * 32 * 4 * 128 * 64]; // partial O per (tile, chunk), fp16
__device__ float  g_lpart[8 * 32 * 4 * 128];      // partial row-sums (fp32)
__device__ unsigned int g_tile_ctr;               // persistent work queue

// ============================ helpers ============================
__device__ __forceinline__ uint32_t smem_u32(const void* p) {
    uint32_t a;
    asm("{ .reg .u64 t; cvta.to.shared.u64 t, %1; cvt.u32.u64 %0, t; }" : "=r"(a) : "l"(p));
    return a;
}
__device__ __forceinline__ void ldsm4(uint32_t addr, uint32_t r[4]) {
    asm volatile("ldmatrix.sync.aligned.m8n8.x4.shared.b16 {%0,%1,%2,%3}, [%4];"
                 : "=r"(r[0]), "=r"(r[1]), "=r"(r[2]), "=r"(r[3]) : "r"(addr));
}
__device__ __forceinline__ void ldsm4t(uint32_t addr, uint32_t r[4]) {
    asm volatile("ldmatrix.sync.aligned.m8n8.x4.trans.shared.b16 {%0,%1,%2,%3}, [%4];"
                 : "=r"(r[0]), "=r"(r[1]), "=r"(r[2]), "=r"(r[3]) : "r"(addr));
}
// D(16x8,f32) += A(16x16,f16) * B(16x8,f16)
__device__ __forceinline__ void mma_f16(float c[4], const uint32_t a[4],
                                        uint32_t b0, uint32_t b1) {
    asm volatile(
        "mma.sync.aligned.m16n8k16.row.col.f32.f16.f16.f32 "
        "{%0,%1,%2,%3}, {%4,%5,%6,%7}, {%8,%9}, {%0,%1,%2,%3};"
        : "+f"(c[0]), "+f"(c[1]), "+f"(c[2]), "+f"(c[3])
        : "r"(a[0]), "r"(a[1]), "r"(a[2]), "r"(a[3]), "r"(b0), "r"(b1));
}
__device__ __forceinline__ uint32_t pkh2(float a, float b) {
    __half2 h = __floats2half2_rn(a, b);
    return *reinterpret_cast<uint32_t*>(&h);
}
__device__ __forceinline__ uint32_t ex2h2(uint32_t x) {  // 2^x on packed half2
    uint32_t r; asm("ex2.approx.f16x2 %0, %1;" : "=r"(r) : "r"(x));
    return r;
}
__device__ __forceinline__ void cpa16(uint32_t s, const void* g) {
    asm volatile("cp.async.cg.shared.global [%0], [%1], 16;" :: "r"(s), "l"(g) : "memory");
}
#define CP_COMMIT() asm volatile("cp.async.commit_group;" ::: "memory")
#define CP_WAIT0()  asm volatile("cp.async.wait_group 0;" ::: "memory")
#define CP_WAIT1()  asm volatile("cp.async.wait_group 1;" ::: "memory")
#define CP_WAIT2()  asm volatile("cp.async.wait_group 2;" ::: "memory")
// fp16 tile row = 64 halfs = 128B = 8 chunks of 16B; chunk XOR-swizzled by row&7
__device__ __forceinline__ uint32_t swzh(int row, int ch) {
    return (uint32_t)((row << 7) + (((ch ^ (row & 7))) << 4));
}

// ============================ tensor-core projections (R13 proven version) ============================
// Block = 128 rows of x, 128 threads. K=65 split: 64 dims via fp16 MMA, remainder
// + bias added fp32 in epilogue. Q scaled by log2(e)/sqrt(65) for ex2 softmax.
__global__ void __launch_bounds__(128) proj_kernel(
    const float* __restrict__ x,
    const float* __restrict__ Wq, const float* __restrict__ bq,
    const float* __restrict__ Wk, const float* __restrict__ bk,
    const float* __restrict__ Wv, const float* __restrict__ bv)
{
    __shared__ __align__(16) __half sX[128 * 64];
    __shared__ __align__(16) __half sWh[64 * 64];
    __shared__ float sx64[128];
    __shared__ float sw64[64];
    __shared__ float sbias[64];

    const int tid  = threadIdx.x;
    const int lane = tid & 31;
    const int w    = tid >> 5;
    const int row0 = blockIdx.x << 7;
    const uint32_t sXb = smem_u32(sX);
    const uint32_t sWb = smem_u32(sWh);
    char* sXc = (char*)sX;
    char* sWc = (char*)sWh;

    if (blockIdx.x == 0 && tid == 0) g_tile_ctr = 0u;

    #pragma unroll
    for (int i = 0; i < 32; i++) {
        const int f = tid + i * 128;
        const int row = f >> 5, d2 = f & 31;
        const size_t gb = (size_t)(row0 + row) * DM + 2 * d2;
        *(uint32_t*)(sXc + swzh(row, d2 >> 2) + ((d2 & 3) << 2)) = pkh2(x[gb], x[gb + 1]);
    }
    sx64[tid] = x[(size_t)(row0 + tid) * DM + 64];

    const int rA = lane & 15, cA = lane >> 4;
    const int rB = (lane & 7) + ((lane >> 4) << 3), cB = (lane >> 3) & 1;
    const int i0 = lane >> 2, q2 = (lane & 3) << 1;

    #pragma unroll
    for (int ph = 0; ph < 2; ph++) {
        const float* W = (ph == 0) ? Wq : Wk;
        const float* bias = (ph == 0) ? bq : bk;
        __half* dst = (ph == 0) ? g_q : g_k;
        const float sc = (ph == 0) ? 0.17894429839f : 1.0f;  // log2(e)/sqrt(65)

        __syncthreads();
        #pragma unroll
        for (int i = 0; i < 8; i++) {
            const int f = tid + i * 128;
            const int d = f >> 4, c4 = (f & 15) << 2;
            const float4 v = *(const float4*)&W[d * 64 + c4];
            char* p = sWc + swzh(d, c4 >> 3) + ((c4 & 7) << 1);
            *(uint32_t*)p       = pkh2(v.x, v.y);
            *(uint32_t*)(p + 4) = pkh2(v.z, v.w);
        }
        if (tid < 64) { sw64[tid] = W[64 * 64 + tid]; sbias[tid] = bias[tid]; }
        __syncthreads();

        uint32_t qa[2][4][4];
        #pragma unroll
        for (int rb = 0; rb < 2; rb++)
            #pragma unroll
            for (int ks = 0; ks < 4; ks++)
                ldsm4(sXb + swzh(32 * w + 16 * rb + rA, 2 * ks + cA), qa[rb][ks]);

        float acc[2][8][4];
        #pragma unroll
        for (int rb = 0; rb < 2; rb++)
            #pragma unroll
            for (int t = 0; t < 8; t++)
                #pragma unroll
                for (int e = 0; e < 4; e++) acc[rb][t][e] = 0.f;

        #pragma unroll
        for (int ks = 0; ks < 4; ks++)
            #pragma unroll
            for (int tp = 0; tp < 4; tp++) {
                uint32_t bt[4];
                ldsm4t(sWb + swzh(16 * ks + rA, 2 * tp + cA), bt);
                #pragma unroll
                for (int rb = 0; rb < 2; rb++) {
                    mma_f16(acc[rb][2 * tp],     qa[rb][ks], bt[0], bt[1]);
                    mma_f16(acc[rb][2 * tp + 1], qa[rb][ks], bt[2], bt[3]);
                }
            }

        #pragma unroll
        for (int rb = 0; rb < 2; rb++) {
            const int r0l = 32 * w + 16 * rb + i0;
            const int r1l = r0l + 8;
            const float x0 = sx64[r0l], x1 = sx64[r1l];
            #pragma unroll
            for (int t = 0; t < 8; t++) {
                const int col = 8 * t + q2;
                const float b0 = sbias[col], b1 = sbias[col + 1];
                const float w0 = sw64[col], w1 = sw64[col + 1];
                *(uint32_t*)&dst[(size_t)(row0 + r0l) * 64 + col] =
                    pkh2((acc[rb][t][0] + b0 + x0 * w0) * sc, (acc[rb][t][1] + b1 + x0 * w1) * sc);
                *(uint32_t*)&dst[(size_t)(row0 + r1l) * 64 + col] =
                    pkh2((acc[rb][t][2] + b0 + x1 * w0) * sc, (acc[rb][t][3] + b1 + x1 * w1) * sc);
            }
        }
    }

    // ---- phase 2: V^T ----
    {
        __syncthreads();
        #pragma unroll
        for (int i = 0; i < 8; i++) {
            const int f = tid + i * 128;
            const int d = f >> 4, c4 = (f & 15) << 2;
            const float4 v = *(const float4*)&Wv[d * 64 + c4];
            char* p = sWc + swzh(d, c4 >> 3) + ((c4 & 7) << 1);
            *(uint32_t*)p       = pkh2(v.x, v.y);
            *(uint32_t*)(p + 4) = pkh2(v.z, v.w);
        }
        if (tid < 64) { sw64[tid] = Wv[64 * 64 + tid]; sbias[tid] = bv[tid]; }
        __syncthreads();

        uint32_t aw[4][4];
        #pragma unroll
        for (int ks = 0; ks < 4; ks++)
            ldsm4t(sWb + swzh(16 * ks + rB, 2 * w + cB), aw[ks]);

        float acc[16][4];
        #pragma unroll
        for (int t = 0; t < 16; t++)
            #pragma unroll
            for (int e = 0; e < 4; e++) acc[t][e] = 0.f;

        #pragma unroll
        for (int tpl = 0; tpl < 8; tpl++)
            #pragma unroll
            for (int ks = 0; ks < 4; ks++) {
                uint32_t xb[4];
                ldsm4(sXb + swzh(16 * tpl + rB, 2 * ks + cB), xb);
                mma_f16(acc[2 * tpl],     aw[ks], xb[0], xb[1]);
                mma_f16(acc[2 * tpl + 1], aw[ks], xb[2], xb[3]);
            }

        const int bb = row0 >> 12, l0 = row0 & 4095;
        const int dim0 = 16 * w + i0, dim1 = dim0 + 8;
        const float bw0 = sbias[dim0], bw1 = sbias[dim1];
        const float w0 = sw64[dim0], w1 = sw64[dim1];
        #pragma unroll
        for (int t = 0; t < 16; t++) {
            const int col = 8 * t + q2;
            const float xa = sx64[col], xb2 = sx64[col + 1];
            *(uint32_t*)&g_vT[(size_t)((bb << 6) + dim0) * SEQ + l0 + col] =
                pkh2(acc[t][0] + bw0 + w0 * xa, acc[t][1] + bw0 + w0 * xb2);
            *(uint32_t*)&g_vT[(size_t)((bb << 6) + dim1) * SEQ + l0 + col] =
                pkh2(acc[t][2] + bw1 + w1 * xa, acc[t][3] + bw1 + w1 * xb2);
        }
    }
}

// ============================ flash (fp16 mma, split-K, P in registers) ============================
// Softmax: pack masked fp32 scores to half2, one ex2.approx.f16x2 -> P fragment
// directly. Row-sums via ones-MMA. Partial O stored fp16 (halved traffic).
__global__ void __launch_bounds__(128, 2) flash_kernel()
{
    __shared__ __align__(16) __half sK[2][64 * 64];
    __shared__ __align__(16) __half sV[2][64 * 64];
    __shared__ __align__(16) __half sQ[128 * 64];   // Q staging; [0] aliased as queue slot

    const uint32_t sKb[2] = { smem_u32(sK[0]), smem_u32(sK[1]) };
    const uint32_t sVb[2] = { smem_u32(sV[0]), smem_u32(sV[1]) };
    const uint32_t sQb = smem_u32(sQ);

    const int tid  = threadIdx.x;
    const int lane = tid & 31;
    const int w    = tid >> 5;
    const int rowA = lane & 15;
    const int chA  = lane >> 4;
    const int rowB = (lane & 7) + ((lane >> 4) << 3);
    const int chB  = (lane >> 3) & 1;
    const int i0   = lane >> 2;
    const int q2   = (lane & 3) << 1;

    for (;;) {
        if (tid == 0)
            *(volatile unsigned*)sQ = atomicAdd(&g_tile_ctr, 1u);
        __syncthreads();
        const unsigned unit = *(volatile unsigned*)sQ;
        __syncthreads();
        if (unit >= NUNITS) break;

        // decode: heavy-first (qt descending), chunks of 16 K-iterations
        const int r = (int)(unit >> 3);
        const int b = (int)(unit & 7u);
        int qt, ch;
        if (r < 32)      { qt = 31 - (r >> 2); ch = r & 3; }
        else if (r < 56) { const int t = r - 32; const int q3 = t / 3; qt = 23 - q3; ch = t - 3 * q3; }
        else if (r < 72) { const int t = r - 56; qt = 15 - (t >> 1); ch = t & 1; }
        else             { qt = 7 - (r - 72); ch = 0; }
        const int nkt = 2 * qt + 2;
        const int kt0 = ch << 4;
        const int kt1 = (kt0 + 16 < nkt) ? kt0 + 16 : nkt;
        const int q0  = qt << 7;

        // ---- async fills: Q, then K/V stage 0 and 1 ----
        #pragma unroll
        for (int i = 0; i < 8; i++) {
            const int f = tid + i * 128;
            const int row = f >> 3, cc = f & 7;
            cpa16(sQb + swzh(row, cc), &g_q[(size_t)((b << 12) + q0 + row) * 64 + cc * 8]);
        }
        CP_COMMIT();
        {
            const int k0 = kt0 << 6;
            #pragma unroll
            for (int i = 0; i < 4; i++) {
                const int f = tid + i * 128;
                const int row = f >> 3, cc = f & 7;
                cpa16(sKb[0] + swzh(row, cc), &g_k[(size_t)((b << 12) + k0 + row) * 64 + cc * 8]);
                cpa16(sVb[0] + swzh(row, cc), &g_vT[(size_t)((b << 6) + row) * SEQ + k0 + cc * 8]);
            }
            CP_COMMIT();
        }
        const bool has2 = (kt0 + 1 < kt1);
        if (has2) {
            const int k0 = (kt0 + 1) << 6;
            #pragma unroll
            for (int i = 0; i < 4; i++) {
                const int f = tid + i * 128;
                const int row = f >> 3, cc = f & 7;
                cpa16(sKb[1] + swzh(row, cc), &g_k[(size_t)((b << 12) + k0 + row) * 64 + cc * 8]);
                cpa16(sVb[1] + swzh(row, cc), &g_vT[(size_t)((b << 6) + row) * SEQ + k0 + cc * 8]);
            }
            CP_COMMIT();
            CP_WAIT2();   // Q group retired
        } else {
            CP_WAIT1();
        }
        __syncthreads();

        // ---- Q fragments (A): 2 row-blocks x 4 k-steps ----
        uint32_t qa[2][4][4];
        #pragma unroll
        for (int rb = 0; rb < 2; rb++)
            #pragma unroll
            for (int ks = 0; ks < 4; ks++)
                ldsm4(sQb + swzh(32 * w + 16 * rb + rowA, 2 * ks + chA), qa[rb][ks]);

        float o[2][8][4];
        #pragma unroll
        for (int rb = 0; rb < 2; rb++)
            #pragma unroll
            for (int t = 0; t < 8; t++)
                #pragma unroll
                for (int e = 0; e < 4; e++) o[rb][t][e] = 0.f;
        float rsacc[2][4];
        #pragma unroll
        for (int rb = 0; rb < 2; rb++)
            #pragma unroll
            for (int e = 0; e < 4; e++) rsacc[rb][e] = 0.f;

        for (int kt = kt0; kt < kt1; kt++) {
            const int cur = (kt - kt0) & 1;
            const int k0  = kt << 6;

            if (kt + 1 < kt1) { CP_WAIT1(); } else { CP_WAIT0(); }
            __syncthreads();   // buf[cur] filled & visible

            // ---- MMA1: S = Q K^T (all 32 mma back-to-back) ----
            float s[2][8][4];
            #pragma unroll
            for (int t = 0; t < 8; t++)
                #pragma unroll
                for (int e = 0; e < 4; e++) { s[0][t][e] = 0.f; s[1][t][e] = 0.f; }
            #pragma unroll
            for (int ks = 0; ks < 4; ks++)
                #pragma unroll
                for (int tp = 0; tp < 4; tp++) {
                    uint32_t kb[4];
                    ldsm4(sKb[cur] + swzh(16 * tp + rowB, 2 * ks + chB), kb);
                    mma_f16(s[0][2 * tp],     qa[0][ks], kb[0], kb[1]);
                    mma_f16(s[0][2 * tp + 1], qa[0][ks], kb[2], kb[3]);
                    mma_f16(s[1][2 * tp],     qa[1][ks], kb[0], kb[1]);
                    mma_f16(s[1][2 * tp + 1], qa[1][ks], kb[2], kb[3]);
                }

            // ---- softmax: mask (fp32), pack half2, ex2.f16x2 -> P A-frags ----
            const bool diag = (kt >= 2 * qt);
            uint32_t pa[2][4][4];
            #pragma unroll
            for (int rb = 0; rb < 2; rb++) {
                const int r0 = q0 + 32 * w + 16 * rb + i0;
                const int r1 = r0 + 8;
                #pragma unroll
                for (int t = 0; t < 8; t++) {
                    float s0 = s[rb][t][0], s1 = s[rb][t][1];
                    float s2 = s[rb][t][2], s3 = s[rb][t][3];
                    if (diag) {
                        const int key = k0 + 8 * t + q2;
                        if (key     > r0) s0 = -1e30f;   // -> half -inf -> ex2 = 0
                        if (key + 1 > r0) s1 = -1e30f;
                        if (key     > r1) s2 = -1e30f;
                        if (key + 1 > r1) s3 = -1e30f;
                    }
                    const uint32_t p01 = ex2h2(pkh2(s0, s1));
                    const uint32_t p23 = ex2h2(pkh2(s2, s3));
                    const int ks = t >> 1;
                    if ((t & 1) == 0) {
                        pa[rb][ks][0] = p01;
                        pa[rb][ks][1] = p23;
                    } else {
                        pa[rb][ks][2] = p01;
                        pa[rb][ks][3] = p23;
                    }
                }
            }

            // ---- MMA2: O += P V ; row-sums via ones-MMA (l = P x 1) ----
            #pragma unroll
            for (int ks = 0; ks < 4; ks++) {
                #pragma unroll
                for (int tp = 0; tp < 4; tp++) {
                    uint32_t vb[4];
                    ldsm4(sVb[cur] + swzh(16 * tp + rowB, 2 * ks + chB), vb);
                    mma_f16(o[0][2 * tp],     pa[0][ks], vb[0], vb[1]);
                    mma_f16(o[0][2 * tp + 1], pa[0][ks], vb[2], vb[3]);
                    mma_f16(o[1][2 * tp],     pa[1][ks], vb[0], vb[1]);
                    mma_f16(o[1][2 * tp + 1], pa[1][ks], vb[2], vb[3]);
                }
                mma_f16(rsacc[0], pa[0][ks], ONE2, ONE2);
                mma_f16(rsacc[1], pa[1][ks], ONE2, ONE2);
            }

            __syncthreads();   // all reads of buf[cur] complete
            if (kt + 2 < kt1) {
                const int kn = (kt + 2) << 6;
                #pragma unroll
                for (int i = 0; i < 4; i++) {
                    const int f = tid + i * 128;
                    const int row = f >> 3, cc = f & 7;
                    cpa16(sKb[cur] + swzh(row, cc), &g_k[(size_t)((b << 12) + kn + row) * 64 + cc * 8]);
                    cpa16(sVb[cur] + swzh(row, cc), &g_vT[(size_t)((b << 6) + row) * SEQ + kn + cc * 8]);
                }
                CP_COMMIT();
            }
        }

        // ---- epilogue: write fp16 un-normalized partials; l from ones-MMA ----
        const int slot = (((b << 5) + qt) << 2) + ch;
        __half* po = &g_part[(size_t)slot << 13];
        #pragma unroll
        for (int rb = 0; rb < 2; rb++) {
            const int r0l = 32 * w + 16 * rb + i0;
            __half* o0 = &po[r0l * 64];
            __half* o1 = o0 + 8 * 64;
            #pragma unroll
            for (int t = 0; t < 8; t++) {
                *(uint32_t*)&o0[8 * t + q2] = pkh2(o[rb][t][0], o[rb][t][1]);
                *(uint32_t*)&o1[8 * t + q2] = pkh2(o[rb][t][2], o[rb][t][3]);
            }
            if ((lane & 3) == 0) {
                g_lpart[slot * 128 + r0l]     = rsacc[rb][0];   // row i0 sum
                g_lpart[slot * 128 + r0l + 8] = rsacc[rb][2];   // row i0+8 sum
            }
        }
    }
}

// ============================ normalize / combine ============================
__global__ void __launch_bounds__(256) norm_kernel(float* __restrict__ out)
{
    const int tile = blockIdx.x;
    const int b = tile >> 5, qt = tile & 31;
    const int nc = (qt + 8) >> 3;
    const int tid = threadIdx.x;
    const int row = tid >> 1;
    const int c0  = (tid & 1) << 5;
    const size_t base = (size_t)tile << 15;

    float acc[32];
    #pragma unroll
    for (int i = 0; i < 32; i++) acc[i] = 0.f;
    float l = 0.f;

    for (int c = 0; c < nc; c++) {
        const __half* p = &g_part[base + ((size_t)c << 13) + row * 64 + c0];
        #pragma unroll
        for (int i = 0; i < 4; i++) {      // 32 halfs = 4 x 16B loads
            const uint4 u = *(const uint4*)&p[i * 8];
            const float2 f0 = __half22float2(*(const __half2*)&u.x);
            const float2 f1 = __half22float2(*(const __half2*)&u.y);
            const float2 f2 = __half22float2(*(const __half2*)&u.z);
            const float2 f3 = __half22float2(*(const __half2*)&u.w);
            acc[8 * i + 0] += f0.x; acc[8 * i + 1] += f0.y;
            acc[8 * i + 2] += f1.x; acc[8 * i + 3] += f1.y;
            acc[8 * i + 4] += f2.x; acc[8 * i + 5] += f2.y;
            acc[8 * i + 6] += f3.x; acc[8 * i + 7] += f3.y;
        }
        l += g_lpart[(tile * 4 + c) * 128 + row];
    }
    const float inv = 1.f / l;
    float* po = &out[(size_t)((b << 12) + (qt << 7) + row) * 64 + c0];
    #pragma unroll
    for (int i = 0; i < 8; i++)
        *(float4*)&po[i * 4] = make_float4(acc[4*i] * inv, acc[4*i+1] * inv,
                                           acc[4*i+2] * inv, acc[4*i+3] * inv);
}

// ============================ launch ============================
extern "C" void kernel_launch(void* const* d_in, const int* in_sizes, int n_in,
                              void* d_out, int out_size)
{
    const float* x  = (const float*)d_in[0];
    const float* Wq = (const float*)d_in[1];
    const float* bq = (const float*)d_in[2];
    const float* Wk = (const float*)d_in[3];
    const float* bk = (const float*)d_in[4];
    const float* Wv = (const float*)d_in[5];
    const float* bv = (const float*)d_in[6];
    float* out = (float*)d_out;

    proj_kernel<<<(BATCH * SEQ) / 128, 128>>>(x, Wq, bq, Wk, bk, Wv, bv);
    flash_kernel<<<296, 128>>>();          // persistent, 2 CTAs/SM, 640 units
    norm_kernel<<<256, 256>>>(out);
}